// round 16
// baseline (speedup 1.0000x reference)
#include <cuda_runtime.h>
#include <cuda_fp16.h>
#include <cstdint>

#define NN  100000
#define EE  1600000
#define IND 128
#define PED 16
#define FIN 144
#define HID 128
#define LAT 64
#define S1  576   // 4*FIN
#define S2  512   // 4*HID
#define SCAN_BLKS ((NN + 1023) / 1024)

// ---------------- scratch (static device globals; no runtime allocation) ----
__device__ __half  g_T1[(size_t)NN * S1];   // [T0|T1|T2|T3] width FIN, fp16
__device__ __half  g_T2[(size_t)NN * S2];   // [T0|T1|T2|T3] width HID, fp16
__device__ __half2 g_W1p[(S1 / 2) * 128];   // W packed: [k2][n] = (W[2k2][n], W[2k2+1][n])
__device__ __half2 g_W2p[(S2 / 2) * 128];
__device__ float g_deg[NN];
__device__ float g_dinv[NN];
__device__ int   g_cnt[NN];
__device__ int   g_inc[NN];
__device__ int   g_rowptr[NN + 1];
__device__ int   g_cursor[NN];
__device__ int   g_bsum[128];
__device__ int   g_bexc[128];
__device__ int   g_csrc[EE];
__device__ float g_cw[EE];
__device__ float g_gsum[HID];

// ---------------- helpers ----------------------------------------------------
__device__ __forceinline__ void mma_f16(float* d, const uint32_t* a, const uint32_t* b) {
    asm volatile(
        "mma.sync.aligned.m16n8k16.row.col.f32.f16.f16.f32 "
        "{%0,%1,%2,%3}, {%4,%5,%6,%7}, {%8,%9}, {%0,%1,%2,%3};"
        : "+f"(d[0]), "+f"(d[1]), "+f"(d[2]), "+f"(d[3])
        : "r"(a[0]), "r"(a[1]), "r"(a[2]), "r"(a[3]), "r"(b[0]), "r"(b[1]));
}
__device__ __forceinline__ void ldsm_x4(uint32_t* r, uint32_t addr) {
    asm volatile("ldmatrix.sync.aligned.m8n8.x4.shared.b16 {%0,%1,%2,%3}, [%4];"
                 : "=r"(r[0]), "=r"(r[1]), "=r"(r[2]), "=r"(r[3]) : "r"(addr));
}
__device__ __forceinline__ void cpa16(uint32_t dst, const void* src, uint32_t bytes) {
    asm volatile("cp.async.cg.shared.global [%0], [%1], 16, %2;"
                 :: "r"(dst), "l"(src), "r"(bytes));
}
#define CPA_COMMIT() asm volatile("cp.async.commit_group;" ::: "memory")
#define CPA_WAIT1()  asm volatile("cp.async.wait_group 1;" ::: "memory")

// ---------------- preprocessing kernels -------------------------------------
__global__ void zero_kernel() {
    int i = blockIdx.x * blockDim.x + threadIdx.x;
    if (i < NN) { g_deg[i] = 0.f; g_cnt[i] = 0; }
    if (i < HID) g_gsum[i] = 0.f;
}

__global__ void deg_cnt_kernel(const int* __restrict__ ei, const float* __restrict__ ew) {
    int e = blockIdx.x * blockDim.x + threadIdx.x;
    if (e >= EE) return;
    int s = ei[e], d = ei[EE + e];
    float w = ew[e];
    if (s == d) w = 0.f;                 // ChebConv removes self loops
    atomicAdd(&g_deg[s], w);
    atomicAdd(&g_cnt[d], 1);
}

// scan over cnt + dinv computation fused
__global__ void scan1_kernel(int n) {
    __shared__ int sh[1024];
    int tid = threadIdx.x;
    int i = blockIdx.x * 1024 + tid;
    if (i < n) {
        float dg = g_deg[i];
        g_dinv[i] = (dg > 0.f) ? rsqrtf(dg) : 0.f;
    }
    int v = (i < n) ? g_cnt[i] : 0;
    sh[tid] = v;
    __syncthreads();
    for (int off = 1; off < 1024; off <<= 1) {
        int t = (tid >= off) ? sh[tid - off] : 0;
        __syncthreads();
        sh[tid] += t;
        __syncthreads();
    }
    if (i < n) g_inc[i] = sh[tid];
    if (tid == 1023) g_bsum[blockIdx.x] = sh[1023];
}

__global__ void scan2_kernel(int nb) {
    __shared__ int sh[128];
    int tid = threadIdx.x;
    int v = (tid < nb) ? g_bsum[tid] : 0;
    sh[tid] = v;
    __syncthreads();
    for (int off = 1; off < 128; off <<= 1) {
        int t = (tid >= off) ? sh[tid - off] : 0;
        __syncthreads();
        sh[tid] += t;
        __syncthreads();
    }
    if (tid < nb) g_bexc[tid] = sh[tid] - v;   // exclusive block offsets
}

// rowptr + cursor init fused
__global__ void scan3_kernel(int n) {
    int i = blockIdx.x * 1024 + threadIdx.x;
    if (i < n) {
        int rp = g_inc[i] + g_bexc[blockIdx.x];
        g_rowptr[i + 1] = rp;
        if (i + 1 < n) g_cursor[i + 1] = rp;
    }
    if (i == 0) { g_rowptr[0] = 0; g_cursor[0] = 0; }
}

__global__ void scatter_kernel(const int* __restrict__ ei, const float* __restrict__ ew) {
    int e = blockIdx.x * blockDim.x + threadIdx.x;
    if (e >= EE) return;
    int s = ei[e], d = ei[EE + e];
    float w = ew[e];
    if (s == d) w = 0.f;
    float wh = -g_dinv[s] * w * g_dinv[d];   // L_hat = -D^-1/2 A D^-1/2
    int pos = atomicAdd(&g_cursor[d], 1);
    g_csrc[pos] = s;
    g_cw[pos]   = wh;
}

// h0 build: 8 features per thread, vectorized
__global__ void build_h0_kernel(const float* __restrict__ x, const float* __restrict__ pe) {
    int idx = blockIdx.x * blockDim.x + threadIdx.x;
    if (idx >= NN * 18) return;
    int i = idx / 18, l = idx - i * 18;
    float4 a, b;
    if (l < 16) {
        const float4* px = reinterpret_cast<const float4*>(x + (size_t)i * IND + l * 8);
        a = px[0]; b = px[1];
    } else {
        const float4* pp = reinterpret_cast<const float4*>(pe + (size_t)i * PED + (l - 16) * 8);
        a = pp[0]; b = pp[1];
    }
    uint4 o;
    __half2* ho = reinterpret_cast<__half2*>(&o);
    ho[0] = __floats2half2_rn(a.x, a.y);
    ho[1] = __floats2half2_rn(a.z, a.w);
    ho[2] = __floats2half2_rn(b.x, b.y);
    ho[3] = __floats2half2_rn(b.z, b.w);
    *reinterpret_cast<uint4*>(g_T1 + (size_t)i * S1 + l * 8) = o;
}

__global__ void packW_kernel(const float* __restrict__ W, int K2, int which) {
    int idx = blockIdx.x * blockDim.x + threadIdx.x;
    if (idx >= K2 * 128) return;
    int k2 = idx >> 7, n = idx & 127;
    __half2 h = __floats2half2_rn(W[(size_t)(2 * k2) * 128 + n],
                                  W[(size_t)(2 * k2 + 1) * 128 + n]);
    (which ? g_W2p : g_W1p)[idx] = h;
}

// ---------------- SpMM (half, uint4 = 8 feats/lane, unroll 4) ---------------
// ROWS rows per block, LANES uint4-lanes per row. blockDim = ROWS*LANES.
__global__ void spmm8h_kernel(int whichBuf, int S, int LANES, int ROWS,
                              int inOff, int outOff, int prevOff, int recur) {
    __half* T = whichBuf ? g_T2 : g_T1;
    int tid = threadIdx.x;
    int r  = tid / LANES;
    int f8 = tid - r * LANES;
    int i = blockIdx.x * ROWS + r;
    if (i >= NN) return;
    int beg = g_rowptr[i], end = g_rowptr[i + 1];
    const __half* Tin = T + inOff + f8 * 8;
    float acc[8];
#pragma unroll
    for (int q = 0; q < 8; q++) acc[q] = 0.f;
    int e = beg;
    for (; e + 4 <= end; e += 4) {
        int s0 = __ldg(&g_csrc[e]),     s1 = __ldg(&g_csrc[e + 1]);
        int s2 = __ldg(&g_csrc[e + 2]), s3 = __ldg(&g_csrc[e + 3]);
        float w0 = __ldg(&g_cw[e]),     w1 = __ldg(&g_cw[e + 1]);
        float w2 = __ldg(&g_cw[e + 2]), w3 = __ldg(&g_cw[e + 3]);
        uint4 v0 = __ldg(reinterpret_cast<const uint4*>(Tin + (size_t)s0 * S));
        uint4 v1 = __ldg(reinterpret_cast<const uint4*>(Tin + (size_t)s1 * S));
        uint4 v2 = __ldg(reinterpret_cast<const uint4*>(Tin + (size_t)s2 * S));
        uint4 v3 = __ldg(reinterpret_cast<const uint4*>(Tin + (size_t)s3 * S));
        const __half2* h0 = reinterpret_cast<const __half2*>(&v0);
        const __half2* h1 = reinterpret_cast<const __half2*>(&v1);
        const __half2* h2 = reinterpret_cast<const __half2*>(&v2);
        const __half2* h3 = reinterpret_cast<const __half2*>(&v3);
#pragma unroll
        for (int q = 0; q < 4; q++) {
            float2 a = __half22float2(h0[q]);
            float2 b = __half22float2(h1[q]);
            float2 c = __half22float2(h2[q]);
            float2 d = __half22float2(h3[q]);
            acc[2 * q]     += (w0 * a.x + w1 * b.x) + (w2 * c.x + w3 * d.x);
            acc[2 * q + 1] += (w0 * a.y + w1 * b.y) + (w2 * c.y + w3 * d.y);
        }
    }
    for (; e < end; ++e) {
        int s0 = __ldg(&g_csrc[e]);
        float w0 = __ldg(&g_cw[e]);
        uint4 v0 = __ldg(reinterpret_cast<const uint4*>(Tin + (size_t)s0 * S));
        const __half2* h0 = reinterpret_cast<const __half2*>(&v0);
#pragma unroll
        for (int q = 0; q < 4; q++) {
            float2 a = __half22float2(h0[q]);
            acc[2 * q]     += w0 * a.x;
            acc[2 * q + 1] += w0 * a.y;
        }
    }
    if (recur) {
        uint4 pv = *reinterpret_cast<const uint4*>(T + (size_t)i * S + prevOff + f8 * 8);
        const __half2* hp = reinterpret_cast<const __half2*>(&pv);
#pragma unroll
        for (int q = 0; q < 4; q++) {
            float2 p = __half22float2(hp[q]);
            acc[2 * q]     = 2.f * acc[2 * q]     - p.x;
            acc[2 * q + 1] = 2.f * acc[2 * q + 1] - p.y;
        }
    }
    uint4 o;
    __half2* ho = reinterpret_cast<__half2*>(&o);
#pragma unroll
    for (int q = 0; q < 4; q++)
        ho[q] = __floats2half2_rn(acc[2 * q], acc[2 * q + 1]);
    *reinterpret_cast<uint4*>(T + (size_t)i * S + outOff + f8 * 8) = o;
}

// ---------------- fp16 mma.sync GEMM, 3-stage cp.async + ldmatrix A ----------
// Pipeline: wait_group 1 -> sync -> prefetch(kt+2) -> commit -> compute(kt).
// Group algebra: at iter kt committed groups hold chunks 0..kt+1, so wait_group 1
// guarantees chunk kt resident while kt+1 is in flight; prefetch of kt+2 comes
// after the barrier proving all reads of its buffer (iter kt-1) are done.
// MODE 0: A = g_T1 [NN, K=576] half; write half to g_T2 slice0 (stride S2)
// MODE 1: A = g_T2 [NN, K=512] half; column-sum into g_gsum (no store of C)
#define ASZ (128 * 40)     // halves per A stage
#define BSZ (16 * 136)     // half2 per B stage
#define GEMM_SMEM (3 * ASZ * 2 + 3 * BSZ * 4 + 128 * 4)
template <int MODE, int K, int NKT>
__global__ void __launch_bounds__(256)
mma_gemm_kernel(const float* __restrict__ bias) {
    const __half*  A  = (MODE == 0) ? g_T1 : g_T2;
    const __half2* Wp = (MODE == 0) ? g_W1p : g_W2p;
    extern __shared__ char dynsm[];
    __half*  As = reinterpret_cast<__half*>(dynsm);
    __half2* Bs = reinterpret_cast<__half2*>(dynsm + 3 * ASZ * 2);
    float*   cs = reinterpret_cast<float*>(dynsm + 3 * ASZ * 2 + 3 * BSZ * 4);

    int tid = threadIdx.x;
    int lane = tid & 31, wid = tid >> 5;
    int wm = (wid & 1) * 64;        // warp M offset
    int wn = (wid >> 1) * 32;       // warp N offset
    int blockM = blockIdx.x * 128;
    int g = lane >> 2, c = lane & 3;

    // per-thread load coordinates
    int aRow = tid >> 2, aQ = tid & 3;               // A: rows aRow, aRow+64
    int bK2 = tid >> 5, bN4 = tid & 31;              // B: k2 bK2, bK2+8
    int gr0 = blockM + aRow, gr1 = gr0 + 64;
    uint32_t szA0 = (gr0 < NN) ? 16u : 0u;
    uint32_t szA1 = (gr1 < NN) ? 16u : 0u;
    uint32_t dA0[3], dA1[3], dB0[3], dB1[3];
    uint32_t aSm[3];
#pragma unroll
    for (int s = 0; s < 3; s++) {
        dA0[s] = (uint32_t)__cvta_generic_to_shared(&As[s * ASZ + aRow * 40 + aQ * 8]);
        dA1[s] = (uint32_t)__cvta_generic_to_shared(&As[s * ASZ + (aRow + 64) * 40 + aQ * 8]);
        dB0[s] = (uint32_t)__cvta_generic_to_shared(&Bs[s * BSZ + bK2 * 136 + bN4 * 4]);
        dB1[s] = (uint32_t)__cvta_generic_to_shared(&Bs[s * BSZ + (bK2 + 8) * 136 + bN4 * 4]);
        aSm[s] = (uint32_t)__cvta_generic_to_shared(&As[s * ASZ]);
    }
    // ldmatrix per-lane source: matrix m = lane>>3 -> (row-half, k-half)
    int rowsel = (lane & 7) + ((lane >> 3) & 1) * 8;
    int ksel   = (lane >> 4) * 8;
    uint32_t aFragOff = (uint32_t)(((wm + rowsel) * 40 + ksel) * 2);  // bytes

    float acc[4][4][4];
#pragma unroll
    for (int mt = 0; mt < 4; mt++)
#pragma unroll
        for (int nt = 0; nt < 4; nt++)
#pragma unroll
            for (int q = 0; q < 4; q++) acc[mt][nt][q] = 0.f;

    if (MODE == 1 && tid < 128) cs[tid] = 0.f;

    // prologue: stages 0 and 1 as two groups
#pragma unroll
    for (int s = 0; s < 2; s++) {
        int kc = s * 32, kc2 = s * 16;
        cpa16(dA0[s], &A[(size_t)gr0 * K + kc + aQ * 8], szA0);
        cpa16(dA1[s], &A[(size_t)gr1 * K + kc + aQ * 8], szA1);
        cpa16(dB0[s], &Wp[(size_t)(kc2 + bK2) * 128 + bN4 * 4], 16u);
        cpa16(dB1[s], &Wp[(size_t)(kc2 + bK2 + 8) * 128 + bN4 * 4], 16u);
        CPA_COMMIT();
    }

    for (int kt = 0; kt < NKT; kt++) {
        CPA_WAIT1();            // chunk kt resident; kt+1 may fly
        __syncthreads();        // all threads done reading buf (kt+2)%3 (iter kt-1)
        int pf = kt + 2;
        if (pf < NKT) {
            int buf = pf % 3;
            int kc = pf * 32, kc2 = pf * 16;
            cpa16(dA0[buf], &A[(size_t)gr0 * K + kc + aQ * 8], szA0);
            cpa16(dA1[buf], &A[(size_t)gr1 * K + kc + aQ * 8], szA1);
            cpa16(dB0[buf], &Wp[(size_t)(kc2 + bK2) * 128 + bN4 * 4], 16u);
            cpa16(dB1[buf], &Wp[(size_t)(kc2 + bK2 + 8) * 128 + bN4 * 4], 16u);
        }
        CPA_COMMIT();           // commit (possibly empty) keeps group count = kt+3

        int st = kt % 3;
        uint32_t aBase = aSm[st] + aFragOff;
        const uint32_t* Bs32 = reinterpret_cast<const uint32_t*>(Bs + st * BSZ);
#pragma unroll
        for (int ks = 0; ks < 2; ks++) {    // two k16 steps per 32-chunk
            int k2b = ks * 8;
            uint32_t a[4][4];
#pragma unroll
            for (int mt = 0; mt < 4; mt++)
                ldsm_x4(a[mt], aBase + (uint32_t)((mt * 16 * 40 + ks * 16) * 2));
            uint32_t b[4][2];
#pragma unroll
            for (int nt = 0; nt < 4; nt++) {
                int col = wn + nt * 8 + g;
                b[nt][0] = Bs32[(k2b + c) * 136 + col];
                b[nt][1] = Bs32[(k2b + c + 4) * 136 + col];
            }
#pragma unroll
            for (int mt = 0; mt < 4; mt++)
#pragma unroll
                for (int nt = 0; nt < 4; nt++)
                    mma_f16(acc[mt][nt], a[mt], b[nt]);
        }
    }

    // ---- epilogue ----
    if (MODE == 0) {
#pragma unroll
        for (int mt = 0; mt < 4; mt++) {
#pragma unroll
            for (int nt = 0; nt < 4; nt++) {
                int col = wn + nt * 8 + 2 * c;
                float b0 = bias[col], b1 = bias[col + 1];
                int row0 = blockM + wm + mt * 16 + g;
                int row1 = row0 + 8;
                if (row0 < NN) {
                    __half2 o = __floats2half2_rn(fmaxf(acc[mt][nt][0] + b0, 0.f),
                                                  fmaxf(acc[mt][nt][1] + b1, 0.f));
                    *reinterpret_cast<__half2*>(&g_T2[(size_t)row0 * S2 + col]) = o;
                }
                if (row1 < NN) {
                    __half2 o = __floats2half2_rn(fmaxf(acc[mt][nt][2] + b0, 0.f),
                                                  fmaxf(acc[mt][nt][3] + b1, 0.f));
                    *reinterpret_cast<__half2*>(&g_T2[(size_t)row1 * S2 + col]) = o;
                }
            }
        }
    } else {
        __syncthreads();   // cs zero-init visible
#pragma unroll
        for (int nt = 0; nt < 4; nt++) {
            int col = wn + nt * 8 + 2 * c;
            float b0 = bias[col], b1 = bias[col + 1];
            float s0 = 0.f, s1 = 0.f;
#pragma unroll
            for (int mt = 0; mt < 4; mt++) {
                int row0 = blockM + wm + mt * 16 + g;
                int row1 = row0 + 8;
                if (row0 < NN) {
                    s0 += fmaxf(acc[mt][nt][0] + b0, 0.f);
                    s1 += fmaxf(acc[mt][nt][1] + b1, 0.f);
                }
                if (row1 < NN) {
                    s0 += fmaxf(acc[mt][nt][2] + b0, 0.f);
                    s1 += fmaxf(acc[mt][nt][3] + b1, 0.f);
                }
            }
#pragma unroll
            for (int o = 4; o < 32; o <<= 1) {
                s0 += __shfl_xor_sync(0xffffffffu, s0, o);
                s1 += __shfl_xor_sync(0xffffffffu, s1, o);
            }
            if (g == 0) {
                atomicAdd(&cs[col], s0);
                atomicAdd(&cs[col + 1], s1);
            }
        }
        __syncthreads();
        if (tid < 128) atomicAdd(&g_gsum[tid], cs[tid]);
    }
}

// ---------------- head: mu = g@W_mu + b_mu, lv = g@W_lv + b_lv --------------
__global__ void head_kernel(const float* __restrict__ Wmu, const float* __restrict__ bmu,
                            const float* __restrict__ Wlv, const float* __restrict__ blv,
                            float* __restrict__ out, int out_size) {
    int j = threadIdx.x;
    if (j >= 128 || j >= out_size) return;
    const float* W  = (j < 64) ? Wmu : Wlv;
    const float* bb = (j < 64) ? bmu : blv;
    int col = j & 63;
    const float invN = 1.0f / (float)NN;
    float s = 0.f;
#pragma unroll
    for (int f = 0; f < HID; f++)
        s += (g_gsum[f] * invN) * W[f * LAT + col];
    out[j] = s + bb[col];
}

// ---------------- launch -----------------------------------------------------
extern "C" void kernel_launch(void* const* d_in, const int* in_sizes, int n_in,
                              void* d_out, int out_size) {
    const float* x   = (const float*)d_in[0];
    const int*   ei  = (const int*)  d_in[1];
    const float* pe  = (const float*)d_in[2];
    const float* ew  = (const float*)d_in[3];
    const float* W1  = (const float*)d_in[4];
    const float* b1  = (const float*)d_in[5];
    const float* W2  = (const float*)d_in[6];
    const float* b2  = (const float*)d_in[7];
    const float* Wmu = (const float*)d_in[8];
    const float* bmu = (const float*)d_in[9];
    const float* Wlv = (const float*)d_in[10];
    const float* blv = (const float*)d_in[11];
    float* out = (float*)d_out;

    // opt into >48KB dynamic smem (host-side attribute; effective pre-capture)
    cudaFuncSetAttribute(mma_gemm_kernel<0, S1, 18>,
                         cudaFuncAttributeMaxDynamicSharedMemorySize, GEMM_SMEM);
    cudaFuncSetAttribute(mma_gemm_kernel<1, S2, 16>,
                         cudaFuncAttributeMaxDynamicSharedMemorySize, GEMM_SMEM);

    zero_kernel<<<(NN + 255) / 256, 256>>>();
    deg_cnt_kernel<<<(EE + 255) / 256, 256>>>(ei, ew);
    scan1_kernel<<<SCAN_BLKS, 1024>>>(NN);
    scan2_kernel<<<1, 128>>>(SCAN_BLKS);
    scan3_kernel<<<SCAN_BLKS, 1024>>>(NN);
    scatter_kernel<<<(EE + 255) / 256, 256>>>(ei, ew);
    build_h0_kernel<<<(NN * 18 + 255) / 256, 256>>>(x, pe);
    packW_kernel<<<((S1 / 2) * 128 + 255) / 256, 256>>>(W1, S1 / 2, 0);
    packW_kernel<<<((S2 / 2) * 128 + 255) / 256, 256>>>(W2, S2 / 2, 1);

    const int GEMM_BLOCKS = (NN + 127) / 128;

    // ---- ChebConv 1 (F=144 -> 18 uint4 lanes, 16 rows x 18 = 288 thr, 9 warps) ----
    spmm8h_kernel<<<(NN + 15) / 16, 288>>>(0, S1, 18, 16, 0,       FIN,     0,   0);
    spmm8h_kernel<<<(NN + 15) / 16, 288>>>(0, S1, 18, 16, FIN,     2 * FIN, 0,   1);
    spmm8h_kernel<<<(NN + 15) / 16, 288>>>(0, S1, 18, 16, 2 * FIN, 3 * FIN, FIN, 1);
    mma_gemm_kernel<0, S1, 18><<<GEMM_BLOCKS, 256, GEMM_SMEM>>>(b1);

    // ---- ChebConv 2 (F=128 -> 16 uint4 lanes, 8 rows x 16 = 128 thr, 4 warps) ----
    spmm8h_kernel<<<(NN + 7) / 8, 128>>>(1, S2, 16, 8, 0,       HID,     0,   0);
    spmm8h_kernel<<<(NN + 7) / 8, 128>>>(1, S2, 16, 8, HID,     2 * HID, 0,   1);
    spmm8h_kernel<<<(NN + 7) / 8, 128>>>(1, S2, 16, 8, 2 * HID, 3 * HID, HID, 1);
    mma_gemm_kernel<1, S2, 16><<<GEMM_BLOCKS, 256, GEMM_SMEM>>>(b2);

    head_kernel<<<1, 128>>>(Wmu, bmu, Wlv, blv, out, out_size);
}

// round 17
// speedup vs baseline: 1.5046x; 1.5046x over previous
#include <cuda_runtime.h>
#include <cuda_fp16.h>
#include <cstdint>

#define NN  100000
#define EE  1600000
#define IND 128
#define PED 16
#define FIN 144
#define HID 128
#define LAT 64
#define S1  576   // 4*FIN
#define S2  512   // 4*HID
#define SCAN_BLKS ((NN + 1023) / 1024)

// ---------------- scratch (static device globals; no runtime allocation) ----
__device__ __half  g_T1[(size_t)NN * S1];   // [T0|T1|T2|T3] width FIN, fp16
__device__ __half  g_T2[(size_t)NN * S2];   // [T0|T1|T2|T3] width HID, fp16
__device__ __half2 g_W1p[(S1 / 2) * 128];   // W packed: [k2][n] = (W[2k2][n], W[2k2+1][n])
__device__ __half2 g_W2p[(S2 / 2) * 128];
__device__ float g_deg[NN];
__device__ float g_dinv[NN];
__device__ int   g_cnt[NN];
__device__ int   g_inc[NN];
__device__ int   g_rowptr[NN + 1];
__device__ int   g_cursor[NN];
__device__ int   g_bsum[128];
__device__ int   g_bexc[128];
__device__ int   g_csrc[EE];
__device__ float g_cw[EE];
__device__ float g_gsum[HID];

// ---------------- helpers ----------------------------------------------------
__device__ __forceinline__ void mma_f16(float* d, const uint32_t* a, const uint32_t* b) {
    asm volatile(
        "mma.sync.aligned.m16n8k16.row.col.f32.f16.f16.f32 "
        "{%0,%1,%2,%3}, {%4,%5,%6,%7}, {%8,%9}, {%0,%1,%2,%3};"
        : "+f"(d[0]), "+f"(d[1]), "+f"(d[2]), "+f"(d[3])
        : "r"(a[0]), "r"(a[1]), "r"(a[2]), "r"(a[3]), "r"(b[0]), "r"(b[1]));
}
__device__ __forceinline__ void ldsm_x4(uint32_t* r, uint32_t addr) {
    asm volatile("ldmatrix.sync.aligned.m8n8.x4.shared.b16 {%0,%1,%2,%3}, [%4];"
                 : "=r"(r[0]), "=r"(r[1]), "=r"(r[2]), "=r"(r[3]) : "r"(addr));
}
__device__ __forceinline__ void cpa16(uint32_t dst, const void* src, uint32_t bytes) {
    asm volatile("cp.async.cg.shared.global [%0], [%1], 16, %2;"
                 :: "r"(dst), "l"(src), "r"(bytes));
}
#define CPA_COMMIT() asm volatile("cp.async.commit_group;" ::: "memory")
#define CPA_WAIT1()  asm volatile("cp.async.wait_group 1;" ::: "memory")

// ---------------- preprocessing kernels -------------------------------------
__global__ void zero_kernel() {
    int i = blockIdx.x * blockDim.x + threadIdx.x;
    if (i < NN) { g_deg[i] = 0.f; g_cnt[i] = 0; }
    if (i < HID) g_gsum[i] = 0.f;
}

__global__ void deg_cnt_kernel(const int* __restrict__ ei, const float* __restrict__ ew) {
    int e = blockIdx.x * blockDim.x + threadIdx.x;
    if (e >= EE) return;
    int s = ei[e], d = ei[EE + e];
    float w = ew[e];
    if (s == d) w = 0.f;                 // ChebConv removes self loops
    atomicAdd(&g_deg[s], w);
    atomicAdd(&g_cnt[d], 1);
}

// scan over cnt + dinv computation fused
__global__ void scan1_kernel(int n) {
    __shared__ int sh[1024];
    int tid = threadIdx.x;
    int i = blockIdx.x * 1024 + tid;
    if (i < n) {
        float dg = g_deg[i];
        g_dinv[i] = (dg > 0.f) ? rsqrtf(dg) : 0.f;
    }
    int v = (i < n) ? g_cnt[i] : 0;
    sh[tid] = v;
    __syncthreads();
    for (int off = 1; off < 1024; off <<= 1) {
        int t = (tid >= off) ? sh[tid - off] : 0;
        __syncthreads();
        sh[tid] += t;
        __syncthreads();
    }
    if (i < n) g_inc[i] = sh[tid];
    if (tid == 1023) g_bsum[blockIdx.x] = sh[1023];
}

__global__ void scan2_kernel(int nb) {
    __shared__ int sh[128];
    int tid = threadIdx.x;
    int v = (tid < nb) ? g_bsum[tid] : 0;
    sh[tid] = v;
    __syncthreads();
    for (int off = 1; off < 128; off <<= 1) {
        int t = (tid >= off) ? sh[tid - off] : 0;
        __syncthreads();
        sh[tid] += t;
        __syncthreads();
    }
    if (tid < nb) g_bexc[tid] = sh[tid] - v;   // exclusive block offsets
}

// rowptr + cursor init fused
__global__ void scan3_kernel(int n) {
    int i = blockIdx.x * 1024 + threadIdx.x;
    if (i < n) {
        int rp = g_inc[i] + g_bexc[blockIdx.x];
        g_rowptr[i + 1] = rp;
        if (i + 1 < n) g_cursor[i + 1] = rp;
    }
    if (i == 0) { g_rowptr[0] = 0; g_cursor[0] = 0; }
}

__global__ void scatter_kernel(const int* __restrict__ ei, const float* __restrict__ ew) {
    int e = blockIdx.x * blockDim.x + threadIdx.x;
    if (e >= EE) return;
    int s = ei[e], d = ei[EE + e];
    float w = ew[e];
    if (s == d) w = 0.f;
    float wh = -g_dinv[s] * w * g_dinv[d];   // L_hat = -D^-1/2 A D^-1/2
    int pos = atomicAdd(&g_cursor[d], 1);
    g_csrc[pos] = s;
    g_cw[pos]   = wh;
}

// h0 build: 8 features per thread, vectorized
__global__ void build_h0_kernel(const float* __restrict__ x, const float* __restrict__ pe) {
    int idx = blockIdx.x * blockDim.x + threadIdx.x;
    if (idx >= NN * 18) return;
    int i = idx / 18, l = idx - i * 18;
    float4 a, b;
    if (l < 16) {
        const float4* px = reinterpret_cast<const float4*>(x + (size_t)i * IND + l * 8);
        a = px[0]; b = px[1];
    } else {
        const float4* pp = reinterpret_cast<const float4*>(pe + (size_t)i * PED + (l - 16) * 8);
        a = pp[0]; b = pp[1];
    }
    uint4 o;
    __half2* ho = reinterpret_cast<__half2*>(&o);
    ho[0] = __floats2half2_rn(a.x, a.y);
    ho[1] = __floats2half2_rn(a.z, a.w);
    ho[2] = __floats2half2_rn(b.x, b.y);
    ho[3] = __floats2half2_rn(b.z, b.w);
    *reinterpret_cast<uint4*>(g_T1 + (size_t)i * S1 + l * 8) = o;
}

__global__ void packW_kernel(const float* __restrict__ W, int K2, int which) {
    int idx = blockIdx.x * blockDim.x + threadIdx.x;
    if (idx >= K2 * 128) return;
    int k2 = idx >> 7, n = idx & 127;
    __half2 h = __floats2half2_rn(W[(size_t)(2 * k2) * 128 + n],
                                  W[(size_t)(2 * k2 + 1) * 128 + n]);
    (which ? g_W2p : g_W1p)[idx] = h;
}

// ---------------- SpMM (half, uint4 = 8 feats/lane, unroll 8) ---------------
// ROWS rows per block, LANES uint4-lanes per row. blockDim = ROWS*LANES.
__global__ void spmm8h_kernel(int whichBuf, int S, int LANES, int ROWS,
                              int inOff, int outOff, int prevOff, int recur) {
    __half* T = whichBuf ? g_T2 : g_T1;
    int tid = threadIdx.x;
    int r  = tid / LANES;
    int f8 = tid - r * LANES;
    int i = blockIdx.x * ROWS + r;
    if (i >= NN) return;
    int beg = g_rowptr[i], end = g_rowptr[i + 1];
    const __half* Tin = T + inOff + f8 * 8;
    float acc[8];
#pragma unroll
    for (int q = 0; q < 8; q++) acc[q] = 0.f;
    int e = beg;
    // unroll 8: 8 independent 16B gathers in flight per thread
    for (; e + 8 <= end; e += 8) {
        int   sE[8];
        float wE[8];
        uint4 vE[8];
#pragma unroll
        for (int u = 0; u < 8; u++) {
            sE[u] = __ldg(&g_csrc[e + u]);
            wE[u] = __ldg(&g_cw[e + u]);
        }
#pragma unroll
        for (int u = 0; u < 8; u++)
            vE[u] = __ldg(reinterpret_cast<const uint4*>(Tin + (size_t)sE[u] * S));
#pragma unroll
        for (int u = 0; u < 8; u++) {
            const __half2* h = reinterpret_cast<const __half2*>(&vE[u]);
            float w = wE[u];
#pragma unroll
            for (int q = 0; q < 4; q++) {
                float2 a = __half22float2(h[q]);
                acc[2 * q]     += w * a.x;
                acc[2 * q + 1] += w * a.y;
            }
        }
    }
    for (; e + 4 <= end; e += 4) {
        int s0 = __ldg(&g_csrc[e]),     s1 = __ldg(&g_csrc[e + 1]);
        int s2 = __ldg(&g_csrc[e + 2]), s3 = __ldg(&g_csrc[e + 3]);
        float w0 = __ldg(&g_cw[e]),     w1 = __ldg(&g_cw[e + 1]);
        float w2 = __ldg(&g_cw[e + 2]), w3 = __ldg(&g_cw[e + 3]);
        uint4 v0 = __ldg(reinterpret_cast<const uint4*>(Tin + (size_t)s0 * S));
        uint4 v1 = __ldg(reinterpret_cast<const uint4*>(Tin + (size_t)s1 * S));
        uint4 v2 = __ldg(reinterpret_cast<const uint4*>(Tin + (size_t)s2 * S));
        uint4 v3 = __ldg(reinterpret_cast<const uint4*>(Tin + (size_t)s3 * S));
        const __half2* h0 = reinterpret_cast<const __half2*>(&v0);
        const __half2* h1 = reinterpret_cast<const __half2*>(&v1);
        const __half2* h2 = reinterpret_cast<const __half2*>(&v2);
        const __half2* h3 = reinterpret_cast<const __half2*>(&v3);
#pragma unroll
        for (int q = 0; q < 4; q++) {
            float2 a = __half22float2(h0[q]);
            float2 b = __half22float2(h1[q]);
            float2 c = __half22float2(h2[q]);
            float2 d = __half22float2(h3[q]);
            acc[2 * q]     += (w0 * a.x + w1 * b.x) + (w2 * c.x + w3 * d.x);
            acc[2 * q + 1] += (w0 * a.y + w1 * b.y) + (w2 * c.y + w3 * d.y);
        }
    }
    for (; e < end; ++e) {
        int s0 = __ldg(&g_csrc[e]);
        float w0 = __ldg(&g_cw[e]);
        uint4 v0 = __ldg(reinterpret_cast<const uint4*>(Tin + (size_t)s0 * S));
        const __half2* h0 = reinterpret_cast<const __half2*>(&v0);
#pragma unroll
        for (int q = 0; q < 4; q++) {
            float2 a = __half22float2(h0[q]);
            acc[2 * q]     += w0 * a.x;
            acc[2 * q + 1] += w0 * a.y;
        }
    }
    if (recur) {
        uint4 pv = *reinterpret_cast<const uint4*>(T + (size_t)i * S + prevOff + f8 * 8);
        const __half2* hp = reinterpret_cast<const __half2*>(&pv);
#pragma unroll
        for (int q = 0; q < 4; q++) {
            float2 p = __half22float2(hp[q]);
            acc[2 * q]     = 2.f * acc[2 * q]     - p.x;
            acc[2 * q + 1] = 2.f * acc[2 * q + 1] - p.y;
        }
    }
    uint4 o;
    __half2* ho = reinterpret_cast<__half2*>(&o);
#pragma unroll
    for (int q = 0; q < 4; q++)
        ho[q] = __floats2half2_rn(acc[2 * q], acc[2 * q + 1]);
    *reinterpret_cast<uint4*>(T + (size_t)i * S + outOff + f8 * 8) = o;
}

// ---------------- fp16 mma.sync GEMM, 2-stage cp.async + ldmatrix A ----------
// (R15 proven configuration — static SMEM, high occupancy. Do not modify.)
// MODE 0: A = g_T1 [NN, K=576] half; write half to g_T2 slice0 (stride S2)
// MODE 1: A = g_T2 [NN, K=512] half; column-sum into g_gsum (no store of C)
template <int MODE, int K, int NKT>
__global__ void __launch_bounds__(256)
mma_gemm_kernel(const float* __restrict__ bias) {
    const __half*  A  = (MODE == 0) ? g_T1 : g_T2;
    const __half2* Wp = (MODE == 0) ? g_W1p : g_W2p;
    __shared__ alignas(16) __half  As[2][128 * 40];   // [row][k], stride 40 halves
    __shared__ alignas(16) __half2 Bs[2][16 * 136];   // [k2][n],  stride 136 half2
    __shared__ float cs[128];

    int tid = threadIdx.x;
    int lane = tid & 31, wid = tid >> 5;
    int wm = (wid & 1) * 64;        // warp M offset
    int wn = (wid >> 1) * 32;       // warp N offset
    int blockM = blockIdx.x * 128;
    int g = lane >> 2, c = lane & 3;

    // per-thread load coordinates
    int aRow = tid >> 2, aQ = tid & 3;               // A: rows aRow, aRow+64
    int bK2 = tid >> 5, bN4 = tid & 31;              // B: k2 bK2, bK2+8
    int gr0 = blockM + aRow, gr1 = gr0 + 64;
    uint32_t szA0 = (gr0 < NN) ? 16u : 0u;
    uint32_t szA1 = (gr1 < NN) ? 16u : 0u;
    uint32_t dA0[2], dA1[2], dB0[2], dB1[2];
    uint32_t aSm[2];
#pragma unroll
    for (int s = 0; s < 2; s++) {
        dA0[s] = (uint32_t)__cvta_generic_to_shared(&As[s][aRow * 40 + aQ * 8]);
        dA1[s] = (uint32_t)__cvta_generic_to_shared(&As[s][(aRow + 64) * 40 + aQ * 8]);
        dB0[s] = (uint32_t)__cvta_generic_to_shared(&Bs[s][bK2 * 136 + bN4 * 4]);
        dB1[s] = (uint32_t)__cvta_generic_to_shared(&Bs[s][(bK2 + 8) * 136 + bN4 * 4]);
        aSm[s] = (uint32_t)__cvta_generic_to_shared(&As[s][0]);
    }
    // ldmatrix per-lane source: matrix m = lane>>3 -> (row-half, k-half)
    int rowsel = (lane & 7) + ((lane >> 3) & 1) * 8;
    int ksel   = (lane >> 4) * 8;
    uint32_t aFragOff = (uint32_t)(((wm + rowsel) * 40 + ksel) * 2);  // bytes

    float acc[4][4][4];
#pragma unroll
    for (int mt = 0; mt < 4; mt++)
#pragma unroll
        for (int nt = 0; nt < 4; nt++)
#pragma unroll
            for (int q = 0; q < 4; q++) acc[mt][nt][q] = 0.f;

    if (MODE == 1 && tid < 128) cs[tid] = 0.f;

    // prologue: stage 0
    {
        cpa16(dA0[0], &A[(size_t)gr0 * K + aQ * 8], szA0);
        cpa16(dA1[0], &A[(size_t)gr1 * K + aQ * 8], szA1);
        cpa16(dB0[0], &Wp[(size_t)bK2 * 128 + bN4 * 4], 16u);
        cpa16(dB1[0], &Wp[(size_t)(bK2 + 8) * 128 + bN4 * 4], 16u);
    }
    CPA_COMMIT();

    for (int kt = 0; kt < NKT; kt++) {
        if (kt + 1 < NKT) {
            int kc = (kt + 1) * 32, kc2 = (kt + 1) * 16;
            int buf = (kt + 1) & 1;
            cpa16(dA0[buf], &A[(size_t)gr0 * K + kc + aQ * 8], szA0);
            cpa16(dA1[buf], &A[(size_t)gr1 * K + kc + aQ * 8], szA1);
            cpa16(dB0[buf], &Wp[(size_t)(kc2 + bK2) * 128 + bN4 * 4], 16u);
            cpa16(dB1[buf], &Wp[(size_t)(kc2 + bK2 + 8) * 128 + bN4 * 4], 16u);
        }
        CPA_COMMIT();
        CPA_WAIT1();
        __syncthreads();

        uint32_t aBase = aSm[kt & 1] + aFragOff;
        const uint32_t* Bs32 = reinterpret_cast<const uint32_t*>(Bs[kt & 1]);
#pragma unroll
        for (int ks = 0; ks < 2; ks++) {    // two k16 steps per 32-chunk
            int k2b = ks * 8;
            uint32_t a[4][4];
#pragma unroll
            for (int mt = 0; mt < 4; mt++)
                ldsm_x4(a[mt], aBase + (uint32_t)((mt * 16 * 40 + ks * 16) * 2));
            uint32_t b[4][2];
#pragma unroll
            for (int nt = 0; nt < 4; nt++) {
                int col = wn + nt * 8 + g;
                b[nt][0] = Bs32[(k2b + c) * 136 + col];
                b[nt][1] = Bs32[(k2b + c + 4) * 136 + col];
            }
#pragma unroll
            for (int mt = 0; mt < 4; mt++)
#pragma unroll
                for (int nt = 0; nt < 4; nt++)
                    mma_f16(acc[mt][nt], a[mt], b[nt]);
        }
        __syncthreads();
    }

    // ---- epilogue ----
    if (MODE == 0) {
#pragma unroll
        for (int mt = 0; mt < 4; mt++) {
#pragma unroll
            for (int nt = 0; nt < 4; nt++) {
                int col = wn + nt * 8 + 2 * c;
                float b0 = bias[col], b1 = bias[col + 1];
                int row0 = blockM + wm + mt * 16 + g;
                int row1 = row0 + 8;
                if (row0 < NN) {
                    __half2 o = __floats2half2_rn(fmaxf(acc[mt][nt][0] + b0, 0.f),
                                                  fmaxf(acc[mt][nt][1] + b1, 0.f));
                    *reinterpret_cast<__half2*>(&g_T2[(size_t)row0 * S2 + col]) = o;
                }
                if (row1 < NN) {
                    __half2 o = __floats2half2_rn(fmaxf(acc[mt][nt][2] + b0, 0.f),
                                                  fmaxf(acc[mt][nt][3] + b1, 0.f));
                    *reinterpret_cast<__half2*>(&g_T2[(size_t)row1 * S2 + col]) = o;
                }
            }
        }
    } else {
#pragma unroll
        for (int nt = 0; nt < 4; nt++) {
            int col = wn + nt * 8 + 2 * c;
            float b0 = bias[col], b1 = bias[col + 1];
            float s0 = 0.f, s1 = 0.f;
#pragma unroll
            for (int mt = 0; mt < 4; mt++) {
                int row0 = blockM + wm + mt * 16 + g;
                int row1 = row0 + 8;
                if (row0 < NN) {
                    s0 += fmaxf(acc[mt][nt][0] + b0, 0.f);
                    s1 += fmaxf(acc[mt][nt][1] + b1, 0.f);
                }
                if (row1 < NN) {
                    s0 += fmaxf(acc[mt][nt][2] + b0, 0.f);
                    s1 += fmaxf(acc[mt][nt][3] + b1, 0.f);
                }
            }
#pragma unroll
            for (int o = 4; o < 32; o <<= 1) {
                s0 += __shfl_xor_sync(0xffffffffu, s0, o);
                s1 += __shfl_xor_sync(0xffffffffu, s1, o);
            }
            if (g == 0) {
                atomicAdd(&cs[col], s0);
                atomicAdd(&cs[col + 1], s1);
            }
        }
        __syncthreads();
        if (tid < 128) atomicAdd(&g_gsum[tid], cs[tid]);
    }
}

// ---------------- head: mu = g@W_mu + b_mu, lv = g@W_lv + b_lv --------------
__global__ void head_kernel(const float* __restrict__ Wmu, const float* __restrict__ bmu,
                            const float* __restrict__ Wlv, const float* __restrict__ blv,
                            float* __restrict__ out, int out_size) {
    int j = threadIdx.x;
    if (j >= 128 || j >= out_size) return;
    const float* W  = (j < 64) ? Wmu : Wlv;
    const float* bb = (j < 64) ? bmu : blv;
    int col = j & 63;
    const float invN = 1.0f / (float)NN;
    float s = 0.f;
#pragma unroll
    for (int f = 0; f < HID; f++)
        s += (g_gsum[f] * invN) * W[f * LAT + col];
    out[j] = s + bb[col];
}

// ---------------- launch -----------------------------------------------------
extern "C" void kernel_launch(void* const* d_in, const int* in_sizes, int n_in,
                              void* d_out, int out_size) {
    const float* x   = (const float*)d_in[0];
    const int*   ei  = (const int*)  d_in[1];
    const float* pe  = (const float*)d_in[2];
    const float* ew  = (const float*)d_in[3];
    const float* W1  = (const float*)d_in[4];
    const float* b1  = (const float*)d_in[5];
    const float* W2  = (const float*)d_in[6];
    const float* b2  = (const float*)d_in[7];
    const float* Wmu = (const float*)d_in[8];
    const float* bmu = (const float*)d_in[9];
    const float* Wlv = (const float*)d_in[10];
    const float* blv = (const float*)d_in[11];
    float* out = (float*)d_out;

    zero_kernel<<<(NN + 255) / 256, 256>>>();
    deg_cnt_kernel<<<(EE + 255) / 256, 256>>>(ei, ew);
    scan1_kernel<<<SCAN_BLKS, 1024>>>(NN);
    scan2_kernel<<<1, 128>>>(SCAN_BLKS);
    scan3_kernel<<<SCAN_BLKS, 1024>>>(NN);
    scatter_kernel<<<(EE + 255) / 256, 256>>>(ei, ew);
    build_h0_kernel<<<(NN * 18 + 255) / 256, 256>>>(x, pe);
    packW_kernel<<<((S1 / 2) * 128 + 255) / 256, 256>>>(W1, S1 / 2, 0);
    packW_kernel<<<((S2 / 2) * 128 + 255) / 256, 256>>>(W2, S2 / 2, 1);

    const int GEMM_BLOCKS = (NN + 127) / 128;

    // ---- ChebConv 1 (F=144 -> 18 uint4 lanes, 16 rows x 18 = 288 thr, 9 warps) ----
    spmm8h_kernel<<<(NN + 15) / 16, 288>>>(0, S1, 18, 16, 0,       FIN,     0,   0);
    spmm8h_kernel<<<(NN + 15) / 16, 288>>>(0, S1, 18, 16, FIN,     2 * FIN, 0,   1);
    spmm8h_kernel<<<(NN + 15) / 16, 288>>>(0, S1, 18, 16, 2 * FIN, 3 * FIN, FIN, 1);
    mma_gemm_kernel<0, S1, 18><<<GEMM_BLOCKS, 256>>>(b1);

    // ---- ChebConv 2 (F=128 -> 16 uint4 lanes, 8 rows x 16 = 128 thr, 4 warps) ----
    spmm8h_kernel<<<(NN + 7) / 8, 128>>>(1, S2, 16, 8, 0,       HID,     0,   0);
    spmm8h_kernel<<<(NN + 7) / 8, 128>>>(1, S2, 16, 8, HID,     2 * HID, 0,   1);
    spmm8h_kernel<<<(NN + 7) / 8, 128>>>(1, S2, 16, 8, 2 * HID, 3 * HID, HID, 1);
    mma_gemm_kernel<1, S2, 16><<<GEMM_BLOCKS, 256>>>(b2);

    head_kernel<<<1, 128>>>(Wmu, bmu, Wlv, blv, out, out_size);
}